// round 10
// baseline (speedup 1.0000x reference)
#include <cuda_runtime.h>
#include <cuda_bf16.h>
#include <cstdint>

// SocialPooling monolith (R9 core) + cp.async double-buffered W staging.
//   stage1: S_g[16 rows x h-half] = M_g[rows x 64(0/1)] @ (H_hi+H_lo)
//   stage2: out_partial += S_hi@W_hi + S_hi@W_lo + S_lo@W_hi  (W from smem)
// CTA = 1 scene, TPB=256: 8 warps = 4 row-strips x 2 k-halves, 2 CTAs/SM.

#define TPB 256

// ---- smem layout ----
#define SM_HHI   0        // bf16 [64 row][128 h] swizzled = 16 KB (reused for staging)
#define SM_HLO   16384    // 16 KB (reused for staging)
#define SM_BM    32768    // u64 [16 cell][64 row] = 8 KB
#define SM_FLAG  40960    // u32[16]
#define SM_PX    41024    // float[64]
#define SM_PY    41280    // float[64]
#define SM_LIST  41536    // u8[16] + int count
#define SM_WBUF  41568    // 2 x 32 KB W double buffer
#define SMEM_MAIN 107104

__device__ uint4 g_wfrags[16 * 8 * 8 * 32];          // [g][k16][n8][lane]

__device__ __forceinline__ uint32_t smem_u32(const void* p) {
    uint32_t a;
    asm("{ .reg .u64 t; cvta.to.shared.u64 t, %1; cvt.u32.u64 %0, t; }" : "=r"(a) : "l"(p));
    return a;
}
__device__ __forceinline__ uint32_t pack_bf16x2(float lo, float hi) {
    uint32_t r;
    asm("cvt.rn.satfinite.bf16x2.f32 %0, %1, %2;" : "=r"(r) : "f"(hi), "f"(lo));
    return r;
}
__device__ __forceinline__ float bflo(uint32_t p) { return __uint_as_float(p << 16); }
__device__ __forceinline__ float bfhi(uint32_t p) { return __uint_as_float(p & 0xFFFF0000u); }

__device__ __forceinline__ uint32_t mbits(unsigned long long v) {
    uint32_t r = (v & 1ull) ? 0x3F80u : 0u;
    if (v & 2ull) r |= 0x3F800000u;
    return r;
}

#define LDMX4T(r0, r1, r2, r3, addr) \
    asm volatile("ldmatrix.sync.aligned.m8n8.x4.trans.shared.b16 {%0,%1,%2,%3}, [%4];" \
                 : "=r"(r0), "=r"(r1), "=r"(r2), "=r"(r3) : "r"(addr))

#define LDS128(v, addr) \
    asm volatile("ld.shared.v4.u32 {%0,%1,%2,%3}, [%4];" \
                 : "=r"((v).x), "=r"((v).y), "=r"((v).z), "=r"((v).w) : "r"(addr))

#define MMA_BF16(d, a0, a1, a2, a3, b0, b1) \
    asm volatile("mma.sync.aligned.m16n8k16.row.col.f32.bf16.bf16.f32 " \
                 "{%0,%1,%2,%3}, {%4,%5,%6,%7}, {%8,%9}, {%0,%1,%2,%3};" \
                 : "+f"((d)[0]), "+f"((d)[1]), "+f"((d)[2]), "+f"((d)[3]) \
                 : "r"(a0), "r"(a1), "r"(a2), "r"(a3), "r"(b0), "r"(b1))

#define CP_COMMIT() asm volatile("cp.async.commit_group;" ::: "memory")
#define CP_WAIT1()  asm volatile("cp.async.wait_group 1;" ::: "memory")

// ---------------- W prep: fragment-order hi/lo split (tiny) ----------------
__global__ void sp_wprep(const float* __restrict__ weight) {
    int idx  = blockIdx.x * 256 + threadIdx.x;   // 0..32767
    int lane = idx & 31;
    int n8   = (idx >> 5) & 7;
    int k16  = (idx >> 8) & 7;
    int g    = idx >> 11;
    int n  = n8 * 8 + (lane >> 2);
    int k0 = g * 128 + k16 * 16 + (lane & 3) * 2;
    float w00 = weight[(size_t)(k0 + 0) * 64 + n];
    float w01 = weight[(size_t)(k0 + 1) * 64 + n];
    float w10 = weight[(size_t)(k0 + 8) * 64 + n];
    float w11 = weight[(size_t)(k0 + 9) * 64 + n];
    uint32_t h0 = pack_bf16x2(w00, w01);
    uint32_t h1 = pack_bf16x2(w10, w11);
    uint32_t l0 = pack_bf16x2(w00 - bflo(h0), w01 - bfhi(h0));
    uint32_t l1 = pack_bf16x2(w10 - bflo(h1), w11 - bfhi(h1));
    g_wfrags[idx] = make_uint4(h0, h1, l0, l1);
}

// issue 32KB cp.async for cell g into buffer at smem offset wb (all 256 threads)
__device__ __forceinline__ void prefetch_w(uint32_t wb, int g, int tid) {
    const uint4* src = g_wfrags + (size_t)g * 2048 + tid;
    const uint32_t dst = wb + (uint32_t)tid * 16;
    #pragma unroll
    for (int it = 0; it < 8; it++) {
        asm volatile("cp.async.cg.shared.global [%0], [%1], 16;"
                     :: "r"(dst + it * 4096), "l"(src + it * 256) : "memory");
    }
}

// ---------------- main: CTA = 1 scene, 8 warps = 4 strips x 2 k-halves ----------------
__global__ __launch_bounds__(TPB, 2)
void sp_main(const float* __restrict__ hidden,
             const float* __restrict__ pos,
             const float* __restrict__ bias,
             float* __restrict__ out)
{
    extern __shared__ char smem[];
    const int tid  = threadIdx.x;
    const int lane = tid & 31;
    const int wid  = tid >> 5;
    const int b    = blockIdx.x;

    unsigned long long* sbm = (unsigned long long*)(smem + SM_BM);
    uint32_t* flag = (uint32_t*)(smem + SM_FLAG);
    float* px = (float*)(smem + SM_PX);
    float* py = (float*)(smem + SM_PY);
    unsigned char* clist = (unsigned char*)(smem + SM_LIST);
    int* nact = (int*)(smem + SM_LIST + 16);

    if (tid < 64) {
        px[tid] = pos[((size_t)b * 64 + tid) * 2 + 0];
        py[tid] = pos[((size_t)b * 64 + tid) * 2 + 1];
    }
    #pragma unroll
    for (int it = 0; it < 4; it++) sbm[tid + it * TPB] = 0ull;

    // H -> smem bf16 hi/lo (once per scene), rows of 256B, 16B-chunk swizzle
    #pragma unroll
    for (int it = 0; it < 4; it++) {
        int cid = tid + it * TPB;          // 0..1023 = row*16 + chunk
        int row = cid >> 4;
        int ch  = cid & 15;
        const float4* src = (const float4*)(hidden + ((size_t)b * 64 + row) * 128 + ch * 8);
        float4 v0 = src[0], v1 = src[1];
        uint32_t h0 = pack_bf16x2(v0.x, v0.y);
        uint32_t h1 = pack_bf16x2(v0.z, v0.w);
        uint32_t h2 = pack_bf16x2(v1.x, v1.y);
        uint32_t h3 = pack_bf16x2(v1.z, v1.w);
        uint32_t l0 = pack_bf16x2(v0.x - bflo(h0), v0.y - bfhi(h0));
        uint32_t l1 = pack_bf16x2(v0.z - bflo(h1), v0.w - bfhi(h1));
        uint32_t l2 = pack_bf16x2(v1.x - bflo(h2), v1.y - bfhi(h2));
        uint32_t l3 = pack_bf16x2(v1.z - bflo(h3), v1.w - bfhi(h3));
        uint32_t off = (uint32_t)(row * 256 + ((ch ^ (row & 7)) << 4));
        *(uint4*)(smem + SM_HHI + off) = make_uint4(h0, h1, h2, h3);
        *(uint4*)(smem + SM_HLO + off) = make_uint4(l0, l1, l2, l3);
    }
    __syncthreads();

    // neighbor bitmasks: 2 threads per row i, disjoint u32 halves of u64
    if (tid < 128) {
        const int i    = tid >> 1;
        const int half = tid & 1;
        const float xi = px[i], yi = py[i];
        const int j0 = half * 32;
        unsigned long long acc[16];
        #pragma unroll
        for (int c = 0; c < 16; c++) acc[c] = 0ull;
        for (int jj = 0; jj < 32; jj++) {
            int j = j0 + jj;
            float dx = px[j] - xi, dy = py[j] - yi;
            if (j != i && fabsf(dx) <= 2.0f && fabsf(dy) <= 2.0f) {
                int gx = min(3, max(0, (int)floorf(dx + 2.0f)));
                int gy = min(3, max(0, (int)floorf(dy + 2.0f)));
                acc[gy * 4 + gx] |= (1ull << j);
            }
        }
        #pragma unroll
        for (int c = 0; c < 16; c++) {
            unsigned int v = (unsigned int)(acc[c] >> (half * 32));
            if (v) ((unsigned int*)&sbm[c * 64 + i])[half] = v;
        }
    }
    __syncthreads();
    if (tid < 16) {
        unsigned long long o = 0;
        #pragma unroll 8
        for (int i = 0; i < 64; i++) o |= sbm[tid * 64 + i];
        flag[tid] = (o != 0ull) ? 1u : 0u;
    }
    __syncthreads();
    if (tid == 0) {
        int n = 0;
        #pragma unroll
        for (int c = 0; c < 16; c++) if (flag[c]) clist[n++] = (unsigned char)c;
        *nact = n;
    }
    __syncthreads();

    // ---- warp mapping: 4 strips x 2 k-halves ----
    const int strip = wid >> 1;
    const int khalf = wid & 1;
    const int il0   = strip * 16;
    const int qr = lane >> 2;
    const int qc = (lane & 3) * 2;

    float oacc[8][4];
    #pragma unroll
    for (int nb = 0; nb < 8; nb++) {
        oacc[nb][0] = 0.f; oacc[nb][1] = 0.f; oacc[nb][2] = 0.f; oacc[nb][3] = 0.f;
    }

    const uint32_t sbu = smem_u32(smem);
    const uint32_t hrow_off = (uint32_t)((((lane >> 3) & 1) * 8 + (lane & 7)) * 256);
    const uint32_t cb = (uint32_t)(lane >> 4);
    const uint32_t l7 = (uint32_t)(lane & 7);

    const int na = *nact;
    if (na > 0) prefetch_w(sbu + SM_WBUF, clist[0], tid);
    CP_COMMIT();

    for (int p = 0; p < na; p++) {
        __syncthreads();    // nobody still reading the buffer we're about to fill
        if (p + 1 < na) prefetch_w(sbu + SM_WBUF + (uint32_t)((p + 1) & 1) * 32768,
                                   clist[p + 1], tid);
        CP_COMMIT();
        CP_WAIT1();         // buffer p complete (≤1 group pending = p+1 prefetch)
        __syncthreads();

        const int g = clist[p];
        const unsigned long long m0 = sbm[g * 64 + il0 + qr];
        const unsigned long long m1 = sbm[g * 64 + il0 + 8 + qr];

        // ---- stage 1: S for our h-half, 8 independent accumulator chains ----
        float sacc[8][4];
        #pragma unroll
        for (int t = 0; t < 8; t++) {
            sacc[t][0] = 0.f; sacc[t][1] = 0.f; sacc[t][2] = 0.f; sacc[t][3] = 0.f;
        }
        #pragma unroll
        for (int t = 0; t < 4; t++) {
            const int sh = t * 16 + qc;
            const uint32_t a0 = mbits(m0 >> sh);
            const uint32_t a1 = mbits(m1 >> sh);
            const uint32_t a2 = mbits(m0 >> (sh + 8));
            const uint32_t a3 = mbits(m1 >> (sh + 8));
            const uint32_t rowoff = hrow_off + (uint32_t)t * 4096;
            #pragma unroll
            for (int hc = 0; hc < 4; hc++) {
                const uint32_t ch  = (uint32_t)(khalf * 8 + hc * 2) + cb;
                const uint32_t off = rowoff + ((ch ^ l7) << 4);
                uint32_t bh0, bh1, bh2, bh3, bl0, bl1, bl2, bl3;
                LDMX4T(bh0, bh1, bh2, bh3, sbu + SM_HHI + off);
                LDMX4T(bl0, bl1, bl2, bl3, sbu + SM_HLO + off);
                MMA_BF16(sacc[2 * hc],     a0, a1, a2, a3, bh0, bh1);
                MMA_BF16(sacc[2 * hc + 1], a0, a1, a2, a3, bh2, bh3);
                MMA_BF16(sacc[2 * hc],     a0, a1, a2, a3, bl0, bl1);
                MMA_BF16(sacc[2 * hc + 1], a0, a1, a2, a3, bl2, bl3);
            }
        }

        // ---- stage 2: our k16 chunks (khalf*4 + hc), W from staged smem ----
        const uint32_t wbuf = sbu + SM_WBUF + (uint32_t)(p & 1) * 32768
                            + (uint32_t)lane * 16;
        #pragma unroll
        for (int hc = 0; hc < 4; hc++) {
            const float* s0 = sacc[2 * hc];
            const float* s1 = sacc[2 * hc + 1];
            uint32_t ah0 = pack_bf16x2(s0[0], s0[1]);
            uint32_t ah1 = pack_bf16x2(s0[2], s0[3]);
            uint32_t ah2 = pack_bf16x2(s1[0], s1[1]);
            uint32_t ah3 = pack_bf16x2(s1[2], s1[3]);
            uint32_t al0 = pack_bf16x2(s0[0] - bflo(ah0), s0[1] - bfhi(ah0));
            uint32_t al1 = pack_bf16x2(s0[2] - bflo(ah1), s0[3] - bfhi(ah1));
            uint32_t al2 = pack_bf16x2(s1[0] - bflo(ah2), s1[1] - bfhi(ah2));
            uint32_t al3 = pack_bf16x2(s1[2] - bflo(ah3), s1[3] - bfhi(ah3));
            const int kk = khalf * 4 + hc;
            const uint32_t wrow = wbuf + (uint32_t)(kk * 4096);
            #pragma unroll
            for (int nbh = 0; nbh < 2; nbh++) {
                uint4 w0, w1, w2, w3;
                LDS128(w0, wrow + (nbh * 4 + 0) * 512);
                LDS128(w1, wrow + (nbh * 4 + 1) * 512);
                LDS128(w2, wrow + (nbh * 4 + 2) * 512);
                LDS128(w3, wrow + (nbh * 4 + 3) * 512);
                float* o0 = oacc[nbh * 4 + 0];
                float* o1 = oacc[nbh * 4 + 1];
                float* o2 = oacc[nbh * 4 + 2];
                float* o3 = oacc[nbh * 4 + 3];
                MMA_BF16(o0, ah0, ah1, ah2, ah3, w0.x, w0.y);
                MMA_BF16(o1, ah0, ah1, ah2, ah3, w1.x, w1.y);
                MMA_BF16(o2, ah0, ah1, ah2, ah3, w2.x, w2.y);
                MMA_BF16(o3, ah0, ah1, ah2, ah3, w3.x, w3.y);
                MMA_BF16(o0, ah0, ah1, ah2, ah3, w0.z, w0.w);
                MMA_BF16(o1, ah0, ah1, ah2, ah3, w1.z, w1.w);
                MMA_BF16(o2, ah0, ah1, ah2, ah3, w2.z, w2.w);
                MMA_BF16(o3, ah0, ah1, ah2, ah3, w3.z, w3.w);
                MMA_BF16(o0, al0, al1, al2, al3, w0.x, w0.y);
                MMA_BF16(o1, al0, al1, al2, al3, w1.x, w1.y);
                MMA_BF16(o2, al0, al1, al2, al3, w2.x, w2.y);
                MMA_BF16(o3, al0, al1, al2, al3, w3.x, w3.y);
            }
        }
    }

    // ---- combine k-halves via smem (reuse H region as fp32 staging) ----
    __syncthreads();                        // all warps done reading H
    float* stg = (float*)(smem + SM_HHI);   // [8 warps][16 rows][64 n] = 32 KB
    {
        float* wbase = stg + wid * 1024;
        #pragma unroll
        for (int nb = 0; nb < 8; nb++) {
            *(float2*)(wbase + qr * 64 + nb * 8 + qc)       = make_float2(oacc[nb][0], oacc[nb][1]);
            *(float2*)(wbase + (qr + 8) * 64 + nb * 8 + qc) = make_float2(oacc[nb][2], oacc[nb][3]);
        }
    }
    __syncthreads();

    // final: out[rl][n] = stg[warp 2s] + stg[warp 2s+1] + bias
    {
        float* orow = out + ((size_t)b * 64) * 64;
        #pragma unroll
        for (int q = 0; q < 4; q++) {
            int e  = tid * 16 + q * 4;
            int rl = e >> 6;
            int n  = e & 63;
            int s  = rl >> 4;
            int rr = rl & 15;
            float4 a = *(float4*)(stg + (2 * s) * 1024 + rr * 64 + n);
            float4 c = *(float4*)(stg + (2 * s + 1) * 1024 + rr * 64 + n);
            float4 bv = *(const float4*)(bias + n);
            *(float4*)(orow + rl * 64 + n) =
                make_float4(a.x + c.x + bv.x, a.y + c.y + bv.y,
                            a.z + c.z + bv.z, a.w + c.w + bv.w);
        }
    }
}

extern "C" void kernel_launch(void* const* d_in, const int* in_sizes, int n_in,
                              void* d_out, int out_size)
{
    const float* hidden = (const float*)d_in[0];
    const float* pos    = (const float*)d_in[1];
    const float* weight = (const float*)d_in[2];
    const float* bias   = (const float*)d_in[3];
    float* out = (float*)d_out;

    const int total = in_sizes[0] / 128;     // 16384 rows
    const int nscene = total / 64;           // 256

    sp_wprep<<<128, 256>>>(weight);

    cudaFuncSetAttribute(sp_main, cudaFuncAttributeMaxDynamicSharedMemorySize, SMEM_MAIN);
    sp_main<<<nscene, TPB, SMEM_MAIN>>>(hidden, pos, bias, out);
}

// round 11
// speedup vs baseline: 1.0846x; 1.0846x over previous
#include <cuda_runtime.h>
#include <cuda_bf16.h>
#include <cstdint>

// SocialPooling, re-associated:  out = sum_c  M_c @ (H @ W_c)
//   stage A: P_c[64j x 64n] = H @ W_c      (bf16 3-term hi/lo, fp32 accum)
//   stage B: out += M_c @ (P_hi + P_lo)    (M exact 0/1, 2-term)
// 20% fewer MMAs than the (M@H)@W order; H fragments reused across cells.
// CTA = 1 scene, TPB=256: 8 warps = 4 j/i-strips x 2 n-halves. 2 CTAs/SM.

#define TPB 256

// ---- smem layout ----
#define SM_H     0        // H bf16: hi [64][256B swz] 16KB + lo 16KB
#define SM_P     32768    // P: 4 slots x (hi 8KB + lo 8KB) = 64 KB
#define SM_BM    98304    // u64 [16 cell][64 row] = 8 KB
#define SM_FLAG  106496   // u32[16]
#define SM_PX    106560   // float[64]
#define SM_PY    106816   // float[64]
#define SM_LIST  107072   // u8[16] + int count
#define SMEM_MAIN 107104

__device__ uint4 g_wfrags[16 * 8 * 8 * 32];          // [g][k16][n8][lane]

__device__ __forceinline__ uint32_t smem_u32(const void* p) {
    uint32_t a;
    asm("{ .reg .u64 t; cvta.to.shared.u64 t, %1; cvt.u32.u64 %0, t; }" : "=r"(a) : "l"(p));
    return a;
}
__device__ __forceinline__ uint32_t pack_bf16x2(float lo, float hi) {
    uint32_t r;
    asm("cvt.rn.satfinite.bf16x2.f32 %0, %1, %2;" : "=r"(r) : "f"(hi), "f"(lo));
    return r;
}
__device__ __forceinline__ float bflo(uint32_t p) { return __uint_as_float(p << 16); }
__device__ __forceinline__ float bfhi(uint32_t p) { return __uint_as_float(p & 0xFFFF0000u); }

__device__ __forceinline__ uint32_t mbits(unsigned long long v) {
    uint32_t r = (v & 1ull) ? 0x3F80u : 0u;
    if (v & 2ull) r |= 0x3F800000u;
    return r;
}

#define LDMX4(r0, r1, r2, r3, addr) \
    asm volatile("ldmatrix.sync.aligned.m8n8.x4.shared.b16 {%0,%1,%2,%3}, [%4];" \
                 : "=r"(r0), "=r"(r1), "=r"(r2), "=r"(r3) : "r"(addr))

#define LDMX4T(r0, r1, r2, r3, addr) \
    asm volatile("ldmatrix.sync.aligned.m8n8.x4.trans.shared.b16 {%0,%1,%2,%3}, [%4];" \
                 : "=r"(r0), "=r"(r1), "=r"(r2), "=r"(r3) : "r"(addr))

#define MMA_BF16(d, a0, a1, a2, a3, b0, b1) \
    asm volatile("mma.sync.aligned.m16n8k16.row.col.f32.bf16.bf16.f32 " \
                 "{%0,%1,%2,%3}, {%4,%5,%6,%7}, {%8,%9}, {%0,%1,%2,%3};" \
                 : "+f"((d)[0]), "+f"((d)[1]), "+f"((d)[2]), "+f"((d)[3]) \
                 : "r"(a0), "r"(a1), "r"(a2), "r"(a3), "r"(b0), "r"(b1))

// P-buffer swizzled offset: 128B rows, 16B chunks XOR row&7
__device__ __forceinline__ uint32_t pswz(uint32_t row, uint32_t nbyte) {
    uint32_t ch = nbyte >> 4;
    return row * 128 + ((ch ^ (row & 7)) << 4) + (nbyte & 15);
}

// ---------------- W prep: fragment-order hi/lo split ----------------
__global__ void sp_wprep(const float* __restrict__ weight) {
    int idx  = blockIdx.x * 256 + threadIdx.x;   // 0..32767
    int lane = idx & 31;
    int n8   = (idx >> 5) & 7;
    int k16  = (idx >> 8) & 7;
    int g    = idx >> 11;
    int n  = n8 * 8 + (lane >> 2);
    int k0 = g * 128 + k16 * 16 + (lane & 3) * 2;
    float w00 = weight[(size_t)(k0 + 0) * 64 + n];
    float w01 = weight[(size_t)(k0 + 1) * 64 + n];
    float w10 = weight[(size_t)(k0 + 8) * 64 + n];
    float w11 = weight[(size_t)(k0 + 9) * 64 + n];
    uint32_t h0 = pack_bf16x2(w00, w01);
    uint32_t h1 = pack_bf16x2(w10, w11);
    uint32_t l0 = pack_bf16x2(w00 - bflo(h0), w01 - bfhi(h0));
    uint32_t l1 = pack_bf16x2(w10 - bflo(h1), w11 - bfhi(h1));
    g_wfrags[idx] = make_uint4(h0, h1, l0, l1);
}

// ---------------- main: CTA = 1 scene ----------------
__global__ __launch_bounds__(TPB, 2)
void sp_main(const float* __restrict__ hidden,
             const float* __restrict__ pos,
             const float* __restrict__ bias,
             float* __restrict__ out)
{
    extern __shared__ char smem[];
    const int tid  = threadIdx.x;
    const int lane = tid & 31;
    const int wid  = tid >> 5;
    const int b    = blockIdx.x;

    unsigned long long* sbm = (unsigned long long*)(smem + SM_BM);
    uint32_t* flag = (uint32_t*)(smem + SM_FLAG);
    float* px = (float*)(smem + SM_PX);
    float* py = (float*)(smem + SM_PY);
    unsigned char* clist = (unsigned char*)(smem + SM_LIST);
    int* nact = (int*)(smem + SM_LIST + 16);

    if (tid < 64) {
        px[tid] = pos[((size_t)b * 64 + tid) * 2 + 0];
        py[tid] = pos[((size_t)b * 64 + tid) * 2 + 1];
    }
    #pragma unroll
    for (int it = 0; it < 4; it++) sbm[tid + it * TPB] = 0ull;

    // H -> smem bf16 hi/lo, rows of 256B, 16B-chunk XOR swizzle
    #pragma unroll
    for (int it = 0; it < 4; it++) {
        int cid = tid + it * TPB;          // 0..1023 = row*16 + chunk
        int row = cid >> 4;
        int ch  = cid & 15;
        const float4* src = (const float4*)(hidden + ((size_t)b * 64 + row) * 128 + ch * 8);
        float4 v0 = src[0], v1 = src[1];
        uint32_t h0 = pack_bf16x2(v0.x, v0.y);
        uint32_t h1 = pack_bf16x2(v0.z, v0.w);
        uint32_t h2 = pack_bf16x2(v1.x, v1.y);
        uint32_t h3 = pack_bf16x2(v1.z, v1.w);
        uint32_t l0 = pack_bf16x2(v0.x - bflo(h0), v0.y - bfhi(h0));
        uint32_t l1 = pack_bf16x2(v0.z - bflo(h1), v0.w - bfhi(h1));
        uint32_t l2 = pack_bf16x2(v1.x - bflo(h2), v1.y - bfhi(h2));
        uint32_t l3 = pack_bf16x2(v1.z - bflo(h3), v1.w - bfhi(h3));
        uint32_t off = (uint32_t)(row * 256 + ((ch ^ (row & 7)) << 4));
        *(uint4*)(smem + SM_H + off)         = make_uint4(h0, h1, h2, h3);
        *(uint4*)(smem + SM_H + 16384 + off) = make_uint4(l0, l1, l2, l3);
    }
    __syncthreads();

    // neighbor bitmasks: 2 threads per row i, disjoint u32 halves of u64
    if (tid < 128) {
        const int i    = tid >> 1;
        const int half = tid & 1;
        const float xi = px[i], yi = py[i];
        const int j0 = half * 32;
        unsigned long long acc[16];
        #pragma unroll
        for (int c = 0; c < 16; c++) acc[c] = 0ull;
        for (int jj = 0; jj < 32; jj++) {
            int j = j0 + jj;
            float dx = px[j] - xi, dy = py[j] - yi;
            if (j != i && fabsf(dx) <= 2.0f && fabsf(dy) <= 2.0f) {
                int gx = min(3, max(0, (int)floorf(dx + 2.0f)));
                int gy = min(3, max(0, (int)floorf(dy + 2.0f)));
                acc[gy * 4 + gx] |= (1ull << j);
            }
        }
        #pragma unroll
        for (int c = 0; c < 16; c++) {
            unsigned int v = (unsigned int)(acc[c] >> (half * 32));
            if (v) ((unsigned int*)&sbm[c * 64 + i])[half] = v;
        }
    }
    __syncthreads();
    if (tid < 16) {
        unsigned long long o = 0;
        #pragma unroll 8
        for (int i = 0; i < 64; i++) o |= sbm[tid * 64 + i];
        flag[tid] = (o != 0ull) ? 1u : 0u;
    }
    __syncthreads();
    if (tid == 0) {
        int n = 0;
        #pragma unroll
        for (int c = 0; c < 16; c++) if (flag[c]) clist[n++] = (unsigned char)c;
        *nact = n;
    }
    __syncthreads();

    // ---- warp mapping: (j/i strip, n-half) ----
    const int js = wid >> 1;               // 0..3
    const int nh = wid & 1;                // 0/1
    const uint32_t sbu = smem_u32(smem);

    float oacc[4][4];                       // [n8 within n32][frag]
    #pragma unroll
    for (int nb = 0; nb < 4; nb++) {
        oacc[nb][0] = 0.f; oacc[nb][1] = 0.f; oacc[nb][2] = 0.f; oacc[nb][3] = 0.f;
    }

    // H A-frag address (non-trans x4): lanes 0-7 rows 0-7, 8-15 rows 8-15,
    // 16-23 rows 0-7 col+8, 24-31 rows 8-15 col+8
    const uint32_t harow = (uint32_t)(js * 16 + (lane & 7) + ((lane >> 3) & 1) * 8);
    const uint32_t hacol = (uint32_t)(lane >> 4);   // extra chunk

    const int na = *nact;
    for (int p0 = 0; p0 < na; p0 += 4) {
        const int nc = min(4, na - p0);
        int gs[4];
        #pragma unroll
        for (int s = 0; s < 4; s++) gs[s] = (s < nc) ? (int)clist[p0 + s] : 0;

        __syncthreads();   // previous chunk's stage B done reading P

        // ---- stage A: P_s = H @ W_{gs}, fp32 accum in regs ----
        float pacc[4][4][4];
        #pragma unroll
        for (int s = 0; s < 4; s++)
            #pragma unroll
            for (int n8 = 0; n8 < 4; n8++) {
                pacc[s][n8][0] = 0.f; pacc[s][n8][1] = 0.f;
                pacc[s][n8][2] = 0.f; pacc[s][n8][3] = 0.f;
            }

        #pragma unroll
        for (int k16 = 0; k16 < 8; k16++) {
            const uint32_t ch  = (uint32_t)(k16 * 2) + hacol;
            const uint32_t off = harow * 256 + ((ch ^ (harow & 7)) << 4);
            uint32_t ah0, ah1, ah2, ah3, al0, al1, al2, al3;
            LDMX4(ah0, ah1, ah2, ah3, sbu + SM_H + off);
            LDMX4(al0, al1, al2, al3, sbu + SM_H + 16384 + off);
            #pragma unroll
            for (int s = 0; s < 4; s++) {
                if (s < nc) {
                    const uint4* wp = g_wfrags
                        + (size_t)((gs[s] * 8 + k16) * 8 + nh * 4) * 32 + lane;
                    #pragma unroll
                    for (int n8 = 0; n8 < 4; n8++) {
                        uint4 w = wp[n8 * 32];
                        MMA_BF16(pacc[s][n8], ah0, ah1, ah2, ah3, w.x, w.y);
                        MMA_BF16(pacc[s][n8], ah0, ah1, ah2, ah3, w.z, w.w);
                        MMA_BF16(pacc[s][n8], al0, al1, al2, al3, w.x, w.y);
                    }
                }
            }
        }

        // ---- write P hi/lo to smem (swizzled 128B rows) ----
        {
            const uint32_t rowA = (uint32_t)(js * 16 + (lane >> 2));
            #pragma unroll
            for (int s = 0; s < 4; s++) {
                if (s < nc) {
                    char* basep = smem + SM_P + s * 16384;
                    #pragma unroll
                    for (int n8 = 0; n8 < 4; n8++) {
                        const float* c = pacc[s][n8];
                        uint32_t hi01 = pack_bf16x2(c[0], c[1]);
                        uint32_t hi23 = pack_bf16x2(c[2], c[3]);
                        uint32_t lo01 = pack_bf16x2(c[0] - bflo(hi01), c[1] - bfhi(hi01));
                        uint32_t lo23 = pack_bf16x2(c[2] - bflo(hi23), c[3] - bfhi(hi23));
                        uint32_t nbyte = (uint32_t)(nh * 64 + n8 * 16 + (lane & 3) * 4);
                        *(uint32_t*)(basep + pswz(rowA, nbyte))          = hi01;
                        *(uint32_t*)(basep + pswz(rowA + 8, nbyte))      = hi23;
                        *(uint32_t*)(basep + 8192 + pswz(rowA, nbyte))   = lo01;
                        *(uint32_t*)(basep + 8192 + pswz(rowA + 8, nbyte)) = lo23;
                    }
                }
            }
        }
        __syncthreads();

        // ---- stage B: out += M_s @ (P_hi + P_lo) ----
        #pragma unroll
        for (int s = 0; s < 4; s++) {
            if (s < nc) {
                const int g = gs[s];
                const unsigned long long m0 = sbm[g * 64 + js * 16 + (lane >> 2)];
                const unsigned long long m1 = sbm[g * 64 + js * 16 + 8 + (lane >> 2)];
                const uint32_t basep = sbu + SM_P + (uint32_t)s * 16384;
                #pragma unroll
                for (int k16b = 0; k16b < 4; k16b++) {
                    const int sh = k16b * 16 + (lane & 3) * 2;
                    const uint32_t a0 = mbits(m0 >> sh);
                    const uint32_t a1 = mbits(m1 >> sh);
                    const uint32_t a2 = mbits(m0 >> (sh + 8));
                    const uint32_t a3 = mbits(m1 >> (sh + 8));
                    const uint32_t rowp = (uint32_t)(k16b * 16 + (lane & 7)
                                                     + ((lane >> 3) & 1) * 8);
                    #pragma unroll
                    for (int nq = 0; nq < 2; nq++) {
                        const uint32_t ch = (uint32_t)(nh * 4 + nq * 2) + (uint32_t)(lane >> 4);
                        const uint32_t offp = rowp * 128 + ((ch ^ (rowp & 7)) << 4);
                        uint32_t ph0, ph1, ph2, ph3, pl0, pl1, pl2, pl3;
                        LDMX4T(ph0, ph1, ph2, ph3, basep + offp);
                        LDMX4T(pl0, pl1, pl2, pl3, basep + 8192 + offp);
                        MMA_BF16(oacc[nq * 2 + 0], a0, a1, a2, a3, ph0, ph1);
                        MMA_BF16(oacc[nq * 2 + 1], a0, a1, a2, a3, ph2, ph3);
                        MMA_BF16(oacc[nq * 2 + 0], a0, a1, a2, a3, pl0, pl1);
                        MMA_BF16(oacc[nq * 2 + 1], a0, a1, a2, a3, pl2, pl3);
                    }
                }
            }
        }
    }

    // ---- epilogue: warps own disjoint quadrants; direct store + bias ----
    {
        const int r    = js * 16 + (lane >> 2);
        const int cb   = nh * 32 + (lane & 3) * 2;
        float* orow = out + ((size_t)b * 64 + r) * 64;
        #pragma unroll
        for (int nb = 0; nb < 4; nb++) {
            const int col = cb + nb * 8;
            float2 bv = *(const float2*)(bias + col);
            *(float2*)(orow + col) =
                make_float2(oacc[nb][0] + bv.x, oacc[nb][1] + bv.y);
            *(float2*)(orow + 8 * 64 + col) =
                make_float2(oacc[nb][2] + bv.x, oacc[nb][3] + bv.y);
        }
    }
}

extern "C" void kernel_launch(void* const* d_in, const int* in_sizes, int n_in,
                              void* d_out, int out_size)
{
    const float* hidden = (const float*)d_in[0];
    const float* pos    = (const float*)d_in[1];
    const float* weight = (const float*)d_in[2];
    const float* bias   = (const float*)d_in[3];
    float* out = (float*)d_out;

    const int total = in_sizes[0] / 128;     // 16384 rows
    const int nscene = total / 64;           // 256

    sp_wprep<<<128, 256>>>(weight);

    cudaFuncSetAttribute(sp_main, cudaFuncAttributeMaxDynamicSharedMemorySize, SMEM_MAIN);
    sp_main<<<nscene, TPB, SMEM_MAIN>>>(hidden, pos, bias, out);
}

// round 12
// speedup vs baseline: 1.2252x; 1.1297x over previous
#include <cuda_runtime.h>
#include <cuda_bf16.h>
#include <cstdint>

// SocialPooling, re-associated:  out = sum_c  M_c @ (H @ W_c)
//   stage A: P_c[64j x 64n] = H @ W_c      (bf16 3-term hi/lo, fp32 accum)
//   stage B: out += M_c @ (P_hi + P_lo)    (M exact 0/1, 2-term)
// R12: term-major MMA scheduling — cells in chunks of 2, W frags in regs,
// same-accumulator reuse spacing 8 (stage A) / 4 (stage B).
// CTA = 1 scene, TPB=256: 8 warps = 4 j/i-strips x 2 n-halves. 2 CTAs/SM.

#define TPB 256

// ---- smem layout ----
#define SM_H     0        // H bf16: hi [64][256B swz] 16KB + lo 16KB
#define SM_P     32768    // P: 2 slots x (hi 8KB + lo 8KB) = 32 KB
#define SM_BM    65536    // u64 [16 cell][64 row] = 8 KB
#define SM_FLAG  73728    // u32[16]
#define SM_PX    73792    // float[64]
#define SM_PY    74048    // float[64]
#define SM_LIST  74304    // u8[16] + int count
#define SMEM_MAIN 74336

__device__ uint4 g_wfrags[16 * 8 * 8 * 32];          // [g][k16][n8][lane]

__device__ __forceinline__ uint32_t smem_u32(const void* p) {
    uint32_t a;
    asm("{ .reg .u64 t; cvta.to.shared.u64 t, %1; cvt.u32.u64 %0, t; }" : "=r"(a) : "l"(p));
    return a;
}
__device__ __forceinline__ uint32_t pack_bf16x2(float lo, float hi) {
    uint32_t r;
    asm("cvt.rn.satfinite.bf16x2.f32 %0, %1, %2;" : "=r"(r) : "f"(hi), "f"(lo));
    return r;
}
__device__ __forceinline__ float bflo(uint32_t p) { return __uint_as_float(p << 16); }
__device__ __forceinline__ float bfhi(uint32_t p) { return __uint_as_float(p & 0xFFFF0000u); }

__device__ __forceinline__ uint32_t mbits(unsigned long long v) {
    uint32_t r = (v & 1ull) ? 0x3F80u : 0u;
    if (v & 2ull) r |= 0x3F800000u;
    return r;
}

#define LDMX4(r0, r1, r2, r3, addr) \
    asm volatile("ldmatrix.sync.aligned.m8n8.x4.shared.b16 {%0,%1,%2,%3}, [%4];" \
                 : "=r"(r0), "=r"(r1), "=r"(r2), "=r"(r3) : "r"(addr))

#define LDMX4T(r0, r1, r2, r3, addr) \
    asm volatile("ldmatrix.sync.aligned.m8n8.x4.trans.shared.b16 {%0,%1,%2,%3}, [%4];" \
                 : "=r"(r0), "=r"(r1), "=r"(r2), "=r"(r3) : "r"(addr))

#define MMA_BF16(d, a0, a1, a2, a3, b0, b1) \
    asm volatile("mma.sync.aligned.m16n8k16.row.col.f32.bf16.bf16.f32 " \
                 "{%0,%1,%2,%3}, {%4,%5,%6,%7}, {%8,%9}, {%0,%1,%2,%3};" \
                 : "+f"((d)[0]), "+f"((d)[1]), "+f"((d)[2]), "+f"((d)[3]) \
                 : "r"(a0), "r"(a1), "r"(a2), "r"(a3), "r"(b0), "r"(b1))

// P-buffer swizzled offset: 128B rows, 16B chunks XOR row&7
__device__ __forceinline__ uint32_t pswz(uint32_t row, uint32_t nbyte) {
    uint32_t ch = nbyte >> 4;
    return row * 128 + ((ch ^ (row & 7)) << 4) + (nbyte & 15);
}

// ---------------- W prep: fragment-order hi/lo split ----------------
__global__ void sp_wprep(const float* __restrict__ weight) {
    int idx  = blockIdx.x * 256 + threadIdx.x;   // 0..32767
    int lane = idx & 31;
    int n8   = (idx >> 5) & 7;
    int k16  = (idx >> 8) & 7;
    int g    = idx >> 11;
    int n  = n8 * 8 + (lane >> 2);
    int k0 = g * 128 + k16 * 16 + (lane & 3) * 2;
    float w00 = weight[(size_t)(k0 + 0) * 64 + n];
    float w01 = weight[(size_t)(k0 + 1) * 64 + n];
    float w10 = weight[(size_t)(k0 + 8) * 64 + n];
    float w11 = weight[(size_t)(k0 + 9) * 64 + n];
    uint32_t h0 = pack_bf16x2(w00, w01);
    uint32_t h1 = pack_bf16x2(w10, w11);
    uint32_t l0 = pack_bf16x2(w00 - bflo(h0), w01 - bfhi(h0));
    uint32_t l1 = pack_bf16x2(w10 - bflo(h1), w11 - bfhi(h1));
    g_wfrags[idx] = make_uint4(h0, h1, l0, l1);
}

// ---------------- main: CTA = 1 scene ----------------
__global__ __launch_bounds__(TPB, 2)
void sp_main(const float* __restrict__ hidden,
             const float* __restrict__ pos,
             const float* __restrict__ bias,
             float* __restrict__ out)
{
    extern __shared__ char smem[];
    const int tid  = threadIdx.x;
    const int lane = tid & 31;
    const int wid  = tid >> 5;
    const int b    = blockIdx.x;

    unsigned long long* sbm = (unsigned long long*)(smem + SM_BM);
    uint32_t* flag = (uint32_t*)(smem + SM_FLAG);
    float* px = (float*)(smem + SM_PX);
    float* py = (float*)(smem + SM_PY);
    unsigned char* clist = (unsigned char*)(smem + SM_LIST);
    int* nact = (int*)(smem + SM_LIST + 16);

    if (tid < 64) {
        px[tid] = pos[((size_t)b * 64 + tid) * 2 + 0];
        py[tid] = pos[((size_t)b * 64 + tid) * 2 + 1];
    }
    #pragma unroll
    for (int it = 0; it < 4; it++) sbm[tid + it * TPB] = 0ull;

    // H -> smem bf16 hi/lo, rows of 256B, 16B-chunk XOR swizzle
    #pragma unroll
    for (int it = 0; it < 4; it++) {
        int cid = tid + it * TPB;          // 0..1023 = row*16 + chunk
        int row = cid >> 4;
        int ch  = cid & 15;
        const float4* src = (const float4*)(hidden + ((size_t)b * 64 + row) * 128 + ch * 8);
        float4 v0 = src[0], v1 = src[1];
        uint32_t h0 = pack_bf16x2(v0.x, v0.y);
        uint32_t h1 = pack_bf16x2(v0.z, v0.w);
        uint32_t h2 = pack_bf16x2(v1.x, v1.y);
        uint32_t h3 = pack_bf16x2(v1.z, v1.w);
        uint32_t l0 = pack_bf16x2(v0.x - bflo(h0), v0.y - bfhi(h0));
        uint32_t l1 = pack_bf16x2(v0.z - bflo(h1), v0.w - bfhi(h1));
        uint32_t l2 = pack_bf16x2(v1.x - bflo(h2), v1.y - bfhi(h2));
        uint32_t l3 = pack_bf16x2(v1.z - bflo(h3), v1.w - bfhi(h3));
        uint32_t off = (uint32_t)(row * 256 + ((ch ^ (row & 7)) << 4));
        *(uint4*)(smem + SM_H + off)         = make_uint4(h0, h1, h2, h3);
        *(uint4*)(smem + SM_H + 16384 + off) = make_uint4(l0, l1, l2, l3);
    }
    __syncthreads();

    // neighbor bitmasks: 2 threads per row i, disjoint u32 halves of u64
    if (tid < 128) {
        const int i    = tid >> 1;
        const int half = tid & 1;
        const float xi = px[i], yi = py[i];
        const int j0 = half * 32;
        unsigned long long acc[16];
        #pragma unroll
        for (int c = 0; c < 16; c++) acc[c] = 0ull;
        for (int jj = 0; jj < 32; jj++) {
            int j = j0 + jj;
            float dx = px[j] - xi, dy = py[j] - yi;
            if (j != i && fabsf(dx) <= 2.0f && fabsf(dy) <= 2.0f) {
                int gx = min(3, max(0, (int)floorf(dx + 2.0f)));
                int gy = min(3, max(0, (int)floorf(dy + 2.0f)));
                acc[gy * 4 + gx] |= (1ull << j);
            }
        }
        #pragma unroll
        for (int c = 0; c < 16; c++) {
            unsigned int v = (unsigned int)(acc[c] >> (half * 32));
            if (v) ((unsigned int*)&sbm[c * 64 + i])[half] = v;
        }
    }
    __syncthreads();
    if (tid < 16) {
        unsigned long long o = 0;
        #pragma unroll 8
        for (int i = 0; i < 64; i++) o |= sbm[tid * 64 + i];
        flag[tid] = (o != 0ull) ? 1u : 0u;
    }
    __syncthreads();
    if (tid == 0) {
        int n = 0;
        #pragma unroll
        for (int c = 0; c < 16; c++) if (flag[c]) clist[n++] = (unsigned char)c;
        *nact = n;
    }
    __syncthreads();

    // ---- warp mapping: (j/i strip, n-half) ----
    const int js = wid >> 1;               // 0..3
    const int nh = wid & 1;                // 0/1
    const uint32_t sbu = smem_u32(smem);

    float oacc[4][4];                       // [n8 within n32][frag]
    #pragma unroll
    for (int nb = 0; nb < 4; nb++) {
        oacc[nb][0] = 0.f; oacc[nb][1] = 0.f; oacc[nb][2] = 0.f; oacc[nb][3] = 0.f;
    }

    // H A-frag address (non-trans x4)
    const uint32_t harow = (uint32_t)(js * 16 + (lane & 7) + ((lane >> 3) & 1) * 8);
    const uint32_t hacol = (uint32_t)(lane >> 4);

    const int na = *nact;
    for (int p0 = 0; p0 < na; p0 += 2) {
        const int nc = min(2, na - p0);
        const int g0 = clist[p0];
        const int g1 = (nc > 1) ? (int)clist[p0 + 1] : g0;   // pad with g0 (B skipped)

        __syncthreads();   // previous chunk's stage B done reading P

        // ---- stage A: P_{g0,g1} = H @ W, term-major (spacing 8) ----
        float pacc[2][4][4];
        #pragma unroll
        for (int s = 0; s < 2; s++)
            #pragma unroll
            for (int n8 = 0; n8 < 4; n8++) {
                pacc[s][n8][0] = 0.f; pacc[s][n8][1] = 0.f;
                pacc[s][n8][2] = 0.f; pacc[s][n8][3] = 0.f;
            }

        #pragma unroll
        for (int k16 = 0; k16 < 8; k16++) {
            const uint32_t ch  = (uint32_t)(k16 * 2) + hacol;
            const uint32_t off = harow * 256 + ((ch ^ (harow & 7)) << 4);
            uint32_t ah0, ah1, ah2, ah3, al0, al1, al2, al3;
            LDMX4(ah0, ah1, ah2, ah3, sbu + SM_H + off);
            LDMX4(al0, al1, al2, al3, sbu + SM_H + 16384 + off);
            const uint4* wp0 = g_wfrags + (size_t)((g0 * 8 + k16) * 8 + nh * 4) * 32 + lane;
            const uint4* wp1 = g_wfrags + (size_t)((g1 * 8 + k16) * 8 + nh * 4) * 32 + lane;
            uint4 w[2][4];
            #pragma unroll
            for (int n8 = 0; n8 < 4; n8++) { w[0][n8] = wp0[n8 * 32]; w[1][n8] = wp1[n8 * 32]; }
            // term 1: Hhi * Whi  (8 independent)
            #pragma unroll
            for (int s = 0; s < 2; s++)
                #pragma unroll
                for (int n8 = 0; n8 < 4; n8++)
                    MMA_BF16(pacc[s][n8], ah0, ah1, ah2, ah3, w[s][n8].x, w[s][n8].y);
            // term 2: Hhi * Wlo
            #pragma unroll
            for (int s = 0; s < 2; s++)
                #pragma unroll
                for (int n8 = 0; n8 < 4; n8++)
                    MMA_BF16(pacc[s][n8], ah0, ah1, ah2, ah3, w[s][n8].z, w[s][n8].w);
            // term 3: Hlo * Whi
            #pragma unroll
            for (int s = 0; s < 2; s++)
                #pragma unroll
                for (int n8 = 0; n8 < 4; n8++)
                    MMA_BF16(pacc[s][n8], al0, al1, al2, al3, w[s][n8].x, w[s][n8].y);
        }

        // ---- write P hi/lo to smem (swizzled 128B rows) ----
        {
            const uint32_t rowA = (uint32_t)(js * 16 + (lane >> 2));
            #pragma unroll
            for (int s = 0; s < 2; s++) {
                if (s < nc) {
                    char* basep = smem + SM_P + s * 16384;
                    #pragma unroll
                    for (int n8 = 0; n8 < 4; n8++) {
                        const float* c = pacc[s][n8];
                        uint32_t hi01 = pack_bf16x2(c[0], c[1]);
                        uint32_t hi23 = pack_bf16x2(c[2], c[3]);
                        uint32_t lo01 = pack_bf16x2(c[0] - bflo(hi01), c[1] - bfhi(hi01));
                        uint32_t lo23 = pack_bf16x2(c[2] - bflo(hi23), c[3] - bfhi(hi23));
                        uint32_t nbyte = (uint32_t)(nh * 64 + n8 * 16 + (lane & 3) * 4);
                        *(uint32_t*)(basep + pswz(rowA, nbyte))            = hi01;
                        *(uint32_t*)(basep + pswz(rowA + 8, nbyte))        = hi23;
                        *(uint32_t*)(basep + 8192 + pswz(rowA, nbyte))     = lo01;
                        *(uint32_t*)(basep + 8192 + pswz(rowA + 8, nbyte)) = lo23;
                    }
                }
            }
        }
        __syncthreads();

        // ---- stage B: out += M_s @ (P_hi + P_lo), spacing 4 ----
        #pragma unroll
        for (int s = 0; s < 2; s++) {
            if (s < nc) {
                const int g = (s == 0) ? g0 : g1;
                const unsigned long long m0 = sbm[g * 64 + js * 16 + (lane >> 2)];
                const unsigned long long m1 = sbm[g * 64 + js * 16 + 8 + (lane >> 2)];
                const uint32_t basep = sbu + SM_P + (uint32_t)s * 16384;
                #pragma unroll
                for (int k16b = 0; k16b < 4; k16b++) {
                    const int sh = k16b * 16 + (lane & 3) * 2;
                    const uint32_t a0 = mbits(m0 >> sh);
                    const uint32_t a1 = mbits(m1 >> sh);
                    const uint32_t a2 = mbits(m0 >> (sh + 8));
                    const uint32_t a3 = mbits(m1 >> (sh + 8));
                    const uint32_t rowp = (uint32_t)(k16b * 16 + (lane & 7)
                                                     + ((lane >> 3) & 1) * 8);
                    // load all 4 P fragment quads (nq0/nq1, hi/lo)
                    const uint32_t ch0 = (uint32_t)(nh * 4) + (uint32_t)(lane >> 4);
                    const uint32_t ch1 = ch0 + 2;
                    const uint32_t off0 = rowp * 128 + ((ch0 ^ (rowp & 7)) << 4);
                    const uint32_t off1 = rowp * 128 + ((ch1 ^ (rowp & 7)) << 4);
                    uint32_t ph0, ph1, ph2, ph3, pl0, pl1, pl2, pl3;
                    uint32_t qh0, qh1, qh2, qh3, ql0, ql1, ql2, ql3;
                    LDMX4T(ph0, ph1, ph2, ph3, basep + off0);
                    LDMX4T(pl0, pl1, pl2, pl3, basep + 8192 + off0);
                    LDMX4T(qh0, qh1, qh2, qh3, basep + off1);
                    LDMX4T(ql0, ql1, ql2, ql3, basep + 8192 + off1);
                    MMA_BF16(oacc[0], a0, a1, a2, a3, ph0, ph1);
                    MMA_BF16(oacc[1], a0, a1, a2, a3, ph2, ph3);
                    MMA_BF16(oacc[2], a0, a1, a2, a3, qh0, qh1);
                    MMA_BF16(oacc[3], a0, a1, a2, a3, qh2, qh3);
                    MMA_BF16(oacc[0], a0, a1, a2, a3, pl0, pl1);
                    MMA_BF16(oacc[1], a0, a1, a2, a3, pl2, pl3);
                    MMA_BF16(oacc[2], a0, a1, a2, a3, ql0, ql1);
                    MMA_BF16(oacc[3], a0, a1, a2, a3, ql2, ql3);
                }
            }
        }
    }

    // ---- epilogue: warps own disjoint quadrants; direct store + bias ----
    {
        const int r    = js * 16 + (lane >> 2);
        const int cb   = nh * 32 + (lane & 3) * 2;
        float* orow = out + ((size_t)b * 64 + r) * 64;
        #pragma unroll
        for (int nb = 0; nb < 4; nb++) {
            const int col = cb + nb * 8;
            float2 bv = *(const float2*)(bias + col);
            *(float2*)(orow + col) =
                make_float2(oacc[nb][0] + bv.x, oacc[nb][1] + bv.y);
            *(float2*)(orow + 8 * 64 + col) =
                make_float2(oacc[nb][2] + bv.x, oacc[nb][3] + bv.y);
        }
    }
}

extern "C" void kernel_launch(void* const* d_in, const int* in_sizes, int n_in,
                              void* d_out, int out_size)
{
    const float* hidden = (const float*)d_in[0];
    const float* pos    = (const float*)d_in[1];
    const float* weight = (const float*)d_in[2];
    const float* bias   = (const float*)d_in[3];
    float* out = (float*)d_out;

    const int total = in_sizes[0] / 128;     // 16384 rows
    const int nscene = total / 64;           // 256

    sp_wprep<<<128, 256>>>(weight);

    cudaFuncSetAttribute(sp_main, cudaFuncAttributeMaxDynamicSharedMemorySize, SMEM_MAIN);
    sp_main<<<nscene, TPB, SMEM_MAIN>>>(hidden, pos, bias, out);
}

// round 13
// speedup vs baseline: 1.5695x; 1.2810x over previous
#include <cuda_runtime.h>
#include <cuda_fp16.h>
#include <cstdint>

// SocialPooling, re-associated, full fp16 tensor path (no hi/lo splits):
//   stage A: P_c[64j x 64n] = fl16(H) @ fl16(W_c)   (fp32 accum)
//   stage B: out += M_c @ fl16(P_c)                 (M exact 0/1)
// Error budget ~5e-4 << 1e-3 threshold; 2.7x fewer MMAs than R12.
// CTA = 1 scene, TPB=256: 8 warps = 4 j/i-strips x 2 n-halves. 2 CTAs/SM.

#define TPB 256

// ---- smem layout ----
#define SM_H     0        // H fp16 [64 row][256B swz] = 16 KB
#define SM_P     16384    // P fp16: 4 slots (2 chunks x 2 cells) x 8KB = 32 KB
#define SM_BM    49152    // u64 [16 cell][64 row] = 8 KB
#define SM_FLAG  57344    // u32[16]
#define SM_PX    57408    // float[64]
#define SM_PY    57664    // float[64]
#define SM_LIST  57920    // u8[16] + int count
#define SMEM_MAIN 57952

// W fp16 fragments: [g][k16][q][lane] uint4 = {n8=2q:(b0,b1), n8=2q+1:(b0,b1)}
__device__ uint4 g_wfrags[16 * 8 * 4 * 32];

__device__ __forceinline__ uint32_t smem_u32(const void* p) {
    uint32_t a;
    asm("{ .reg .u64 t; cvta.to.shared.u64 t, %1; cvt.u32.u64 %0, t; }" : "=r"(a) : "l"(p));
    return a;
}
// pack two fp32 -> fp16x2 (lo arg in low half)
__device__ __forceinline__ uint32_t pack_f16x2(float lo, float hi) {
    uint32_t r;
    asm("cvt.rn.f16x2.f32 %0, %1, %2;" : "=r"(r) : "f"(hi), "f"(lo));
    return r;
}
// two mask bits -> packed fp16x2 of {0.0 or 1.0}
__device__ __forceinline__ uint32_t mbits16(unsigned long long v) {
    uint32_t r = (v & 1ull) ? 0x3C00u : 0u;
    if (v & 2ull) r |= 0x3C000000u;
    return r;
}

#define LDMX4(r0, r1, r2, r3, addr) \
    asm volatile("ldmatrix.sync.aligned.m8n8.x4.shared.b16 {%0,%1,%2,%3}, [%4];" \
                 : "=r"(r0), "=r"(r1), "=r"(r2), "=r"(r3) : "r"(addr))

#define LDMX4T(r0, r1, r2, r3, addr) \
    asm volatile("ldmatrix.sync.aligned.m8n8.x4.trans.shared.b16 {%0,%1,%2,%3}, [%4];" \
                 : "=r"(r0), "=r"(r1), "=r"(r2), "=r"(r3) : "r"(addr))

#define MMA_F16(d, a0, a1, a2, a3, b0, b1) \
    asm volatile("mma.sync.aligned.m16n8k16.row.col.f32.f16.f16.f32 " \
                 "{%0,%1,%2,%3}, {%4,%5,%6,%7}, {%8,%9}, {%0,%1,%2,%3};" \
                 : "+f"((d)[0]), "+f"((d)[1]), "+f"((d)[2]), "+f"((d)[3]) \
                 : "r"(a0), "r"(a1), "r"(a2), "r"(a3), "r"(b0), "r"(b1))

// P-buffer swizzled offset: 128B rows, 16B chunks XOR row&7
__device__ __forceinline__ uint32_t pswz(uint32_t row, uint32_t nbyte) {
    uint32_t ch = nbyte >> 4;
    return row * 128 + ((ch ^ (row & 7)) << 4) + (nbyte & 15);
}

// ---------------- W prep: fp16 fragments, B-fragment order ----------------
__global__ void sp_wprep(const float* __restrict__ weight) {
    int idx  = blockIdx.x * 256 + threadIdx.x;   // 0..16383
    int lane = idx & 31;
    int q    = (idx >> 5) & 3;
    int k16  = (idx >> 7) & 7;
    int g    = idx >> 10;
    int na = (2 * q)     * 8 + (lane >> 2);
    int nb = (2 * q + 1) * 8 + (lane >> 2);
    int k0 = g * 128 + k16 * 16 + (lane & 3) * 2;
    uint4 v;
    v.x = pack_f16x2(weight[(size_t)(k0 + 0) * 64 + na], weight[(size_t)(k0 + 1) * 64 + na]);
    v.y = pack_f16x2(weight[(size_t)(k0 + 8) * 64 + na], weight[(size_t)(k0 + 9) * 64 + na]);
    v.z = pack_f16x2(weight[(size_t)(k0 + 0) * 64 + nb], weight[(size_t)(k0 + 1) * 64 + nb]);
    v.w = pack_f16x2(weight[(size_t)(k0 + 8) * 64 + nb], weight[(size_t)(k0 + 9) * 64 + nb]);
    g_wfrags[idx] = v;
}

// ---------------- main: CTA = 1 scene ----------------
__global__ __launch_bounds__(TPB, 2)
void sp_main(const float* __restrict__ hidden,
             const float* __restrict__ pos,
             const float* __restrict__ bias,
             float* __restrict__ out)
{
    extern __shared__ char smem[];
    const int tid  = threadIdx.x;
    const int lane = tid & 31;
    const int wid  = tid >> 5;
    const int b    = blockIdx.x;

    unsigned long long* sbm = (unsigned long long*)(smem + SM_BM);
    uint32_t* flag = (uint32_t*)(smem + SM_FLAG);
    float* px = (float*)(smem + SM_PX);
    float* py = (float*)(smem + SM_PY);
    unsigned char* clist = (unsigned char*)(smem + SM_LIST);
    int* nact = (int*)(smem + SM_LIST + 16);

    if (tid < 64) {
        px[tid] = pos[((size_t)b * 64 + tid) * 2 + 0];
        py[tid] = pos[((size_t)b * 64 + tid) * 2 + 1];
    }
    #pragma unroll
    for (int it = 0; it < 4; it++) sbm[tid + it * TPB] = 0ull;

    // H -> smem fp16, rows of 256B, 16B-chunk XOR swizzle
    #pragma unroll
    for (int it = 0; it < 4; it++) {
        int cid = tid + it * TPB;          // 0..1023 = row*16 + chunk
        int row = cid >> 4;
        int ch  = cid & 15;
        const float4* src = (const float4*)(hidden + ((size_t)b * 64 + row) * 128 + ch * 8);
        float4 v0 = src[0], v1 = src[1];
        uint4 hv;
        hv.x = pack_f16x2(v0.x, v0.y);
        hv.y = pack_f16x2(v0.z, v0.w);
        hv.z = pack_f16x2(v1.x, v1.y);
        hv.w = pack_f16x2(v1.z, v1.w);
        uint32_t off = (uint32_t)(row * 256 + ((ch ^ (row & 7)) << 4));
        *(uint4*)(smem + SM_H + off) = hv;
    }
    __syncthreads();

    // neighbor bitmasks: 2 threads per row i, disjoint u32 halves of u64
    if (tid < 128) {
        const int i    = tid >> 1;
        const int half = tid & 1;
        const float xi = px[i], yi = py[i];
        const int j0 = half * 32;
        unsigned long long acc[16];
        #pragma unroll
        for (int c = 0; c < 16; c++) acc[c] = 0ull;
        for (int jj = 0; jj < 32; jj++) {
            int j = j0 + jj;
            float dx = px[j] - xi, dy = py[j] - yi;
            if (j != i && fabsf(dx) <= 2.0f && fabsf(dy) <= 2.0f) {
                int gx = min(3, max(0, (int)floorf(dx + 2.0f)));
                int gy = min(3, max(0, (int)floorf(dy + 2.0f)));
                acc[gy * 4 + gx] |= (1ull << j);
            }
        }
        #pragma unroll
        for (int c = 0; c < 16; c++) {
            unsigned int v = (unsigned int)(acc[c] >> (half * 32));
            if (v) ((unsigned int*)&sbm[c * 64 + i])[half] = v;
        }
    }
    __syncthreads();
    if (tid < 16) {
        unsigned long long o = 0;
        #pragma unroll 8
        for (int i = 0; i < 64; i++) o |= sbm[tid * 64 + i];
        flag[tid] = (o != 0ull) ? 1u : 0u;
    }
    __syncthreads();
    if (tid == 0) {
        int n = 0;
        #pragma unroll
        for (int c = 0; c < 16; c++) if (flag[c]) clist[n++] = (unsigned char)c;
        *nact = n;
    }
    __syncthreads();

    // ---- warp mapping: (j/i strip, n-half) ----
    const int js = wid >> 1;               // 0..3
    const int nh = wid & 1;                // 0/1
    const uint32_t sbu = smem_u32(smem);

    float oacc[4][4];
    #pragma unroll
    for (int nb = 0; nb < 4; nb++) {
        oacc[nb][0] = 0.f; oacc[nb][1] = 0.f; oacc[nb][2] = 0.f; oacc[nb][3] = 0.f;
    }

    const uint32_t harow = (uint32_t)(js * 16 + (lane & 7) + ((lane >> 3) & 1) * 8);
    const uint32_t hacol = (uint32_t)(lane >> 4);

    const int na = *nact;
    for (int p0 = 0; p0 < na; p0 += 2) {
        const int nc = min(2, na - p0);
        const int g0 = clist[p0];
        const int g1 = (nc > 1) ? (int)clist[p0 + 1] : g0;
        const uint32_t slotbase = (uint32_t)(((p0 >> 1) & 1) * 16384);

        // ---- stage A: P_{g0,g1} = H @ W, 8 independent accumulators ----
        float pacc[2][4][4];
        #pragma unroll
        for (int s = 0; s < 2; s++)
            #pragma unroll
            for (int n8 = 0; n8 < 4; n8++) {
                pacc[s][n8][0] = 0.f; pacc[s][n8][1] = 0.f;
                pacc[s][n8][2] = 0.f; pacc[s][n8][3] = 0.f;
            }

        #pragma unroll
        for (int k16 = 0; k16 < 8; k16++) {
            const uint32_t ch  = (uint32_t)(k16 * 2) + hacol;
            const uint32_t off = harow * 256 + ((ch ^ (harow & 7)) << 4);
            uint32_t a0, a1, a2, a3;
            LDMX4(a0, a1, a2, a3, sbu + SM_H + off);
            uint4 w[2][2];
            #pragma unroll
            for (int qq = 0; qq < 2; qq++) {
                w[0][qq] = g_wfrags[((g0 * 8 + k16) * 4 + nh * 2 + qq) * 32 + lane];
                w[1][qq] = g_wfrags[((g1 * 8 + k16) * 4 + nh * 2 + qq) * 32 + lane];
            }
            #pragma unroll
            for (int s = 0; s < 2; s++)
                #pragma unroll
                for (int qq = 0; qq < 2; qq++) {
                    MMA_F16(pacc[s][qq * 2],     a0, a1, a2, a3, w[s][qq].x, w[s][qq].y);
                    MMA_F16(pacc[s][qq * 2 + 1], a0, a1, a2, a3, w[s][qq].z, w[s][qq].w);
                }
        }

        // ---- write P fp16 to smem (swizzled 128B rows) ----
        {
            const uint32_t rowA = (uint32_t)(js * 16 + (lane >> 2));
            #pragma unroll
            for (int s = 0; s < 2; s++) {
                if (s < nc) {
                    char* basep = smem + SM_P + slotbase + s * 8192;
                    #pragma unroll
                    for (int n8 = 0; n8 < 4; n8++) {
                        const float* c = pacc[s][n8];
                        uint32_t lo = pack_f16x2(c[0], c[1]);
                        uint32_t hi = pack_f16x2(c[2], c[3]);
                        uint32_t nbyte = (uint32_t)(nh * 64 + n8 * 16 + (lane & 3) * 4);
                        *(uint32_t*)(basep + pswz(rowA, nbyte))     = lo;
                        *(uint32_t*)(basep + pswz(rowA + 8, nbyte)) = hi;
                    }
                }
            }
        }
        __syncthreads();

        // ---- stage B: out += M_s @ P_s ----
        #pragma unroll
        for (int s = 0; s < 2; s++) {
            if (s < nc) {
                const int g = (s == 0) ? g0 : g1;
                const unsigned long long m0 = sbm[g * 64 + js * 16 + (lane >> 2)];
                const unsigned long long m1 = sbm[g * 64 + js * 16 + 8 + (lane >> 2)];
                const uint32_t basep = sbu + SM_P + slotbase + (uint32_t)s * 8192;
                #pragma unroll
                for (int k16b = 0; k16b < 4; k16b++) {
                    const int sh = k16b * 16 + (lane & 3) * 2;
                    const uint32_t a0 = mbits16(m0 >> sh);
                    const uint32_t a1 = mbits16(m1 >> sh);
                    const uint32_t a2 = mbits16(m0 >> (sh + 8));
                    const uint32_t a3 = mbits16(m1 >> (sh + 8));
                    const uint32_t rowp = (uint32_t)(k16b * 16 + (lane & 7)
                                                     + ((lane >> 3) & 1) * 8);
                    const uint32_t ch0 = (uint32_t)(nh * 4) + (uint32_t)(lane >> 4);
                    const uint32_t ch1 = ch0 + 2;
                    const uint32_t off0 = rowp * 128 + ((ch0 ^ (rowp & 7)) << 4);
                    const uint32_t off1 = rowp * 128 + ((ch1 ^ (rowp & 7)) << 4);
                    uint32_t q0, q1, q2, q3, r0, r1, r2, r3;
                    LDMX4T(q0, q1, q2, q3, basep + off0);
                    LDMX4T(r0, r1, r2, r3, basep + off1);
                    MMA_F16(oacc[0], a0, a1, a2, a3, q0, q1);
                    MMA_F16(oacc[1], a0, a1, a2, a3, q2, q3);
                    MMA_F16(oacc[2], a0, a1, a2, a3, r0, r1);
                    MMA_F16(oacc[3], a0, a1, a2, a3, r2, r3);
                }
            }
        }
    }

    // ---- epilogue: warps own disjoint quadrants; direct store + bias ----
    {
        const int r    = js * 16 + (lane >> 2);
        const int cb   = nh * 32 + (lane & 3) * 2;
        float* orow = out + ((size_t)b * 64 + r) * 64;
        #pragma unroll
        for (int nb = 0; nb < 4; nb++) {
            const int col = cb + nb * 8;
            float2 bv = *(const float2*)(bias + col);
            *(float2*)(orow + col) =
                make_float2(oacc[nb][0] + bv.x, oacc[nb][1] + bv.y);
            *(float2*)(orow + 8 * 64 + col) =
                make_float2(oacc[nb][2] + bv.x, oacc[nb][3] + bv.y);
        }
    }
}

extern "C" void kernel_launch(void* const* d_in, const int* in_sizes, int n_in,
                              void* d_out, int out_size)
{
    const float* hidden = (const float*)d_in[0];
    const float* pos    = (const float*)d_in[1];
    const float* weight = (const float*)d_in[2];
    const float* bias   = (const float*)d_in[3];
    float* out = (float*)d_out;

    const int total = in_sizes[0] / 128;     // 16384 rows
    const int nscene = total / 64;           // 256

    sp_wprep<<<64, 256>>>(weight);

    cudaFuncSetAttribute(sp_main, cudaFuncAttributeMaxDynamicSharedMemorySize, SMEM_MAIN);
    sp_main<<<nscene, TPB, SMEM_MAIN>>>(hidden, pos, bias, out);
}

// round 14
// speedup vs baseline: 1.9421x; 1.2374x over previous
#include <cuda_runtime.h>
#include <cuda_fp16.h>
#include <cstdint>

// SocialPooling, re-associated, full fp16 tensor path:
//   stage A: P_c[64j x 64n] = fl16(H) @ fl16(W_c)   (fp32 accum)
//   stage B: out += M_c @ fl16(P_c)                 (M exact 0/1)
// R14: instruction diet — 4-thread/row mask build, redux.sync flags,
// H A-fragments hoisted out of the chunk loop (loaded once into regs).
// CTA = 1 scene, TPB=256: 8 warps = 4 j/i-strips x 2 n-halves. 2 CTAs/SM.

#define TPB 256

// ---- smem layout ----
#define SM_H     0        // H fp16 [64 row][256B swz] = 16 KB
#define SM_P     16384    // P fp16: 4 slots (2 chunks x 2 cells) x 8KB = 32 KB
#define SM_BM    49152    // u64 [16 cell][64 row] = 8 KB
#define SM_WOR   57344    // u32[8] per-warp OR
#define SM_PX    57408    // float[64]
#define SM_PY    57664    // float[64]
#define SM_LIST  57920    // u8[16] + int count
#define SMEM_MAIN 57952

// W fp16 fragments: [g][k16][q][lane] uint4 = {n8=2q:(b0,b1), n8=2q+1:(b0,b1)}
__device__ uint4 g_wfrags[16 * 8 * 4 * 32];

__device__ __forceinline__ uint32_t smem_u32(const void* p) {
    uint32_t a;
    asm("{ .reg .u64 t; cvta.to.shared.u64 t, %1; cvt.u32.u64 %0, t; }" : "=r"(a) : "l"(p));
    return a;
}
__device__ __forceinline__ uint32_t pack_f16x2(float lo, float hi) {
    uint32_t r;
    asm("cvt.rn.f16x2.f32 %0, %1, %2;" : "=r"(r) : "f"(hi), "f"(lo));
    return r;
}
__device__ __forceinline__ uint32_t mbits16(unsigned long long v) {
    uint32_t r = (v & 1ull) ? 0x3C00u : 0u;
    if (v & 2ull) r |= 0x3C000000u;
    return r;
}

#define LDMX4(r0, r1, r2, r3, addr) \
    asm volatile("ldmatrix.sync.aligned.m8n8.x4.shared.b16 {%0,%1,%2,%3}, [%4];" \
                 : "=r"(r0), "=r"(r1), "=r"(r2), "=r"(r3) : "r"(addr))

#define LDMX4T(r0, r1, r2, r3, addr) \
    asm volatile("ldmatrix.sync.aligned.m8n8.x4.trans.shared.b16 {%0,%1,%2,%3}, [%4];" \
                 : "=r"(r0), "=r"(r1), "=r"(r2), "=r"(r3) : "r"(addr))

#define MMA_F16(d, a0, a1, a2, a3, b0, b1) \
    asm volatile("mma.sync.aligned.m16n8k16.row.col.f32.f16.f16.f32 " \
                 "{%0,%1,%2,%3}, {%4,%5,%6,%7}, {%8,%9}, {%0,%1,%2,%3};" \
                 : "+f"((d)[0]), "+f"((d)[1]), "+f"((d)[2]), "+f"((d)[3]) \
                 : "r"(a0), "r"(a1), "r"(a2), "r"(a3), "r"(b0), "r"(b1))

__device__ __forceinline__ uint32_t pswz(uint32_t row, uint32_t nbyte) {
    uint32_t ch = nbyte >> 4;
    return row * 128 + ((ch ^ (row & 7)) << 4) + (nbyte & 15);
}

// ---------------- W prep: fp16 fragments, B-fragment order ----------------
__global__ void sp_wprep(const float* __restrict__ weight) {
    int idx  = blockIdx.x * 256 + threadIdx.x;   // 0..16383
    int lane = idx & 31;
    int q    = (idx >> 5) & 3;
    int k16  = (idx >> 7) & 7;
    int g    = idx >> 10;
    int na = (2 * q)     * 8 + (lane >> 2);
    int nb = (2 * q + 1) * 8 + (lane >> 2);
    int k0 = g * 128 + k16 * 16 + (lane & 3) * 2;
    uint4 v;
    v.x = pack_f16x2(weight[(size_t)(k0 + 0) * 64 + na], weight[(size_t)(k0 + 1) * 64 + na]);
    v.y = pack_f16x2(weight[(size_t)(k0 + 8) * 64 + na], weight[(size_t)(k0 + 9) * 64 + na]);
    v.z = pack_f16x2(weight[(size_t)(k0 + 0) * 64 + nb], weight[(size_t)(k0 + 1) * 64 + nb]);
    v.w = pack_f16x2(weight[(size_t)(k0 + 8) * 64 + nb], weight[(size_t)(k0 + 9) * 64 + nb]);
    g_wfrags[idx] = v;
}

// ---------------- main: CTA = 1 scene ----------------
__global__ __launch_bounds__(TPB, 2)
void sp_main(const float* __restrict__ hidden,
             const float* __restrict__ pos,
             const float* __restrict__ bias,
             float* __restrict__ out)
{
    extern __shared__ char smem[];
    const int tid  = threadIdx.x;
    const int lane = tid & 31;
    const int wid  = tid >> 5;
    const int b    = blockIdx.x;

    unsigned long long* sbm = (unsigned long long*)(smem + SM_BM);
    uint32_t* wor = (uint32_t*)(smem + SM_WOR);
    float* px = (float*)(smem + SM_PX);
    float* py = (float*)(smem + SM_PY);
    unsigned char* clist = (unsigned char*)(smem + SM_LIST);
    int* nact = (int*)(smem + SM_LIST + 16);

    if (tid < 64) {
        px[tid] = pos[((size_t)b * 64 + tid) * 2 + 0];
        py[tid] = pos[((size_t)b * 64 + tid) * 2 + 1];
    }
    #pragma unroll
    for (int it = 0; it < 4; it++) sbm[tid + it * TPB] = 0ull;

    // H -> smem fp16, rows of 256B, 16B-chunk XOR swizzle
    #pragma unroll
    for (int it = 0; it < 4; it++) {
        int cid = tid + it * TPB;          // 0..1023 = row*16 + chunk
        int row = cid >> 4;
        int ch  = cid & 15;
        const float4* src = (const float4*)(hidden + ((size_t)b * 64 + row) * 128 + ch * 8);
        float4 v0 = src[0], v1 = src[1];
        uint4 hv;
        hv.x = pack_f16x2(v0.x, v0.y);
        hv.y = pack_f16x2(v0.z, v0.w);
        hv.z = pack_f16x2(v1.x, v1.y);
        hv.w = pack_f16x2(v1.z, v1.w);
        uint32_t off = (uint32_t)(row * 256 + ((ch ^ (row & 7)) << 4));
        *(uint4*)(smem + SM_H + off) = hv;
    }
    __syncthreads();

    // neighbor bitmasks: 4 threads per row (disjoint u16 quarters of the u64)
    {
        const int i = tid >> 2;            // row 0..63
        const int q = tid & 3;             // quarter
        const int j0 = q * 16;
        const float xi = px[i], yi = py[i];
        uint32_t acc[16];
        #pragma unroll
        for (int c = 0; c < 16; c++) acc[c] = 0u;
        #pragma unroll
        for (int jj = 0; jj < 16; jj++) {
            int j = j0 + jj;
            float dx = px[j] - xi, dy = py[j] - yi;
            if (j != i && fabsf(dx) <= 2.0f && fabsf(dy) <= 2.0f) {
                int gx = min(3, max(0, (int)floorf(dx + 2.0f)));
                int gy = min(3, max(0, (int)floorf(dy + 2.0f)));
                acc[gy * 4 + gx] |= (1u << jj);
            }
        }
        uint32_t bitmap = 0;
        #pragma unroll
        for (int c = 0; c < 16; c++) {
            if (acc[c]) {
                *(unsigned short*)((char*)&sbm[c * 64 + i] + q * 2) = (unsigned short)acc[c];
                bitmap |= (1u << c);
            }
        }
        uint32_t w_or = __reduce_or_sync(0xffffffffu, bitmap);
        if (lane == 0) wor[wid] = w_or;
    }
    __syncthreads();
    if (tid == 0) {
        uint32_t bm16 = 0;
        #pragma unroll
        for (int w = 0; w < 8; w++) bm16 |= wor[w];
        int n = 0;
        #pragma unroll
        for (int c = 0; c < 16; c++)
            if (bm16 & (1u << c)) clist[n++] = (unsigned char)c;
        *nact = n;
    }
    __syncthreads();

    // ---- warp mapping: (j/i strip, n-half) ----
    const int js = wid >> 1;               // 0..3
    const int nh = wid & 1;                // 0/1
    const uint32_t sbu = smem_u32(smem);

    float oacc[4][4];
    #pragma unroll
    for (int nb = 0; nb < 4; nb++) {
        oacc[nb][0] = 0.f; oacc[nb][1] = 0.f; oacc[nb][2] = 0.f; oacc[nb][3] = 0.f;
    }

    // ---- hoist H A-fragments for all 8 k16 into regs (reused every chunk) ----
    const uint32_t harow = (uint32_t)(js * 16 + (lane & 7) + ((lane >> 3) & 1) * 8);
    const uint32_t hacol = (uint32_t)(lane >> 4);
    uint32_t hf[8][4];
    #pragma unroll
    for (int k16 = 0; k16 < 8; k16++) {
        const uint32_t ch  = (uint32_t)(k16 * 2) + hacol;
        const uint32_t off = harow * 256 + ((ch ^ (harow & 7)) << 4);
        LDMX4(hf[k16][0], hf[k16][1], hf[k16][2], hf[k16][3], sbu + SM_H + off);
    }

    const int na = *nact;
    for (int p0 = 0; p0 < na; p0 += 2) {
        const int nc = min(2, na - p0);
        const int g0 = clist[p0];
        const int g1 = (nc > 1) ? (int)clist[p0 + 1] : g0;
        const uint32_t slotbase = (uint32_t)(((p0 >> 1) & 1) * 16384);

        // ---- stage A: P_{g0,g1} = H @ W (LDG + MMA only) ----
        float pacc[2][4][4];
        #pragma unroll
        for (int s = 0; s < 2; s++)
            #pragma unroll
            for (int n8 = 0; n8 < 4; n8++) {
                pacc[s][n8][0] = 0.f; pacc[s][n8][1] = 0.f;
                pacc[s][n8][2] = 0.f; pacc[s][n8][3] = 0.f;
            }

        #pragma unroll
        for (int k16 = 0; k16 < 8; k16++) {
            uint4 w[2][2];
            #pragma unroll
            for (int qq = 0; qq < 2; qq++) {
                w[0][qq] = g_wfrags[((g0 * 8 + k16) * 4 + nh * 2 + qq) * 32 + lane];
                w[1][qq] = g_wfrags[((g1 * 8 + k16) * 4 + nh * 2 + qq) * 32 + lane];
            }
            #pragma unroll
            for (int s = 0; s < 2; s++)
                #pragma unroll
                for (int qq = 0; qq < 2; qq++) {
                    MMA_F16(pacc[s][qq * 2],     hf[k16][0], hf[k16][1], hf[k16][2], hf[k16][3],
                            w[s][qq].x, w[s][qq].y);
                    MMA_F16(pacc[s][qq * 2 + 1], hf[k16][0], hf[k16][1], hf[k16][2], hf[k16][3],
                            w[s][qq].z, w[s][qq].w);
                }
        }

        // ---- write P fp16 to smem (swizzled 128B rows) ----
        {
            const uint32_t rowA = (uint32_t)(js * 16 + (lane >> 2));
            #pragma unroll
            for (int s = 0; s < 2; s++) {
                if (s < nc) {
                    char* basep = smem + SM_P + slotbase + s * 8192;
                    #pragma unroll
                    for (int n8 = 0; n8 < 4; n8++) {
                        const float* c = pacc[s][n8];
                        uint32_t lo = pack_f16x2(c[0], c[1]);
                        uint32_t hi = pack_f16x2(c[2], c[3]);
                        uint32_t nbyte = (uint32_t)(nh * 64 + n8 * 16 + (lane & 3) * 4);
                        *(uint32_t*)(basep + pswz(rowA, nbyte))     = lo;
                        *(uint32_t*)(basep + pswz(rowA + 8, nbyte)) = hi;
                    }
                }
            }
        }
        __syncthreads();

        // ---- stage B: out += M_s @ P_s ----
        #pragma unroll
        for (int s = 0; s < 2; s++) {
            if (s < nc) {
                const int g = (s == 0) ? g0 : g1;
                const unsigned long long m0 = sbm[g * 64 + js * 16 + (lane >> 2)];
                const unsigned long long m1 = sbm[g * 64 + js * 16 + 8 + (lane >> 2)];
                const uint32_t basep = sbu + SM_P + slotbase + (uint32_t)s * 8192;
                #pragma unroll
                for (int k16b = 0; k16b < 4; k16b++) {
                    const int sh = k16b * 16 + (lane & 3) * 2;
                    const uint32_t a0 = mbits16(m0 >> sh);
                    const uint32_t a1 = mbits16(m1 >> sh);
                    const uint32_t a2 = mbits16(m0 >> (sh + 8));
                    const uint32_t a3 = mbits16(m1 >> (sh + 8));
                    const uint32_t rowp = (uint32_t)(k16b * 16 + (lane & 7)
                                                     + ((lane >> 3) & 1) * 8);
                    const uint32_t ch0 = (uint32_t)(nh * 4) + (uint32_t)(lane >> 4);
                    const uint32_t ch1 = ch0 + 2;
                    const uint32_t off0 = rowp * 128 + ((ch0 ^ (rowp & 7)) << 4);
                    const uint32_t off1 = rowp * 128 + ((ch1 ^ (rowp & 7)) << 4);
                    uint32_t q0, q1, q2, q3, r0, r1, r2, r3;
                    LDMX4T(q0, q1, q2, q3, basep + off0);
                    LDMX4T(r0, r1, r2, r3, basep + off1);
                    MMA_F16(oacc[0], a0, a1, a2, a3, q0, q1);
                    MMA_F16(oacc[1], a0, a1, a2, a3, q2, q3);
                    MMA_F16(oacc[2], a0, a1, a2, a3, r0, r1);
                    MMA_F16(oacc[3], a0, a1, a2, a3, r2, r3);
                }
            }
        }
    }

    // ---- epilogue: warps own disjoint quadrants; direct store + bias ----
    {
        const int r    = js * 16 + (lane >> 2);
        const int cb   = nh * 32 + (lane & 3) * 2;
        float* orow = out + ((size_t)b * 64 + r) * 64;
        #pragma unroll
        for (int nb = 0; nb < 4; nb++) {
            const int col = cb + nb * 8;
            float2 bv = *(const float2*)(bias + col);
            *(float2*)(orow + col) =
                make_float2(oacc[nb][0] + bv.x, oacc[nb][1] + bv.y);
            *(float2*)(orow + 8 * 64 + col) =
                make_float2(oacc[nb][2] + bv.x, oacc[nb][3] + bv.y);
        }
    }
}

extern "C" void kernel_launch(void* const* d_in, const int* in_sizes, int n_in,
                              void* d_out, int out_size)
{
    const float* hidden = (const float*)d_in[0];
    const float* pos    = (const float*)d_in[1];
    const float* weight = (const float*)d_in[2];
    const float* bias   = (const float*)d_in[3];
    float* out = (float*)d_out;

    const int total = in_sizes[0] / 128;     // 16384 rows
    const int nscene = total / 64;           // 256

    sp_wprep<<<64, 256>>>(weight);

    cudaFuncSetAttribute(sp_main, cudaFuncAttributeMaxDynamicSharedMemorySize, SMEM_MAIN);
    sp_main<<<nscene, TPB, SMEM_MAIN>>>(hidden, pos, bias, out);
}

// round 15
// speedup vs baseline: 1.9715x; 1.0152x over previous
#include <cuda_runtime.h>
#include <cuda_fp16.h>
#include <cstdint>

// SocialPooling, re-associated, full fp16 tensor path:
//   stage A: P_c[64j x 64n] = fl16(H) @ fl16(W_c)   (fp32 accum)
//   stage B: out += M_c @ fl16(P_c)                 (M exact 0/1 fp16)
// R15: CTA-cooperative fp16 M-tile expansion in smem (A-fragments via LDMX4
// instead of per-warp ALU expansion). Double-buffered P and M slots.
// CTA = 1 scene, TPB=256: 8 warps = 4 j/i-strips x 2 n-halves. 2 CTAs/SM.

#define TPB 256

// ---- smem layout ----
#define SM_H     0        // H fp16 [64 row][256B swz] = 16 KB
#define SM_P     16384    // P fp16: 2 slots x 2 cells x 8KB = 32 KB
#define SM_M     49152    // M fp16: 2 slots x 2 cells x 8KB = 32 KB
#define SM_BM    81920    // u64 [16 cell][64 row] = 8 KB
#define SM_WOR   90112    // u32[8]
#define SM_PX    90176    // float[64]
#define SM_PY    90432    // float[64]
#define SM_LIST  90688    // u8[16] + int count
#define SMEM_MAIN 90720

// W fp16 fragments: [g][k16][q][lane] uint4
__device__ uint4 g_wfrags[16 * 8 * 4 * 32];

__device__ __forceinline__ uint32_t smem_u32(const void* p) {
    uint32_t a;
    asm("{ .reg .u64 t; cvta.to.shared.u64 t, %1; cvt.u32.u64 %0, t; }" : "=r"(a) : "l"(p));
    return a;
}
__device__ __forceinline__ uint32_t pack_f16x2(float lo, float hi) {
    uint32_t r;
    asm("cvt.rn.f16x2.f32 %0, %1, %2;" : "=r"(r) : "f"(hi), "f"(lo));
    return r;
}
__device__ __forceinline__ uint32_t mbits16(uint32_t v) {
    uint32_t r = (v & 1u) ? 0x3C00u : 0u;
    if (v & 2u) r |= 0x3C000000u;
    return r;
}

#define LDMX4(r0, r1, r2, r3, addr) \
    asm volatile("ldmatrix.sync.aligned.m8n8.x4.shared.b16 {%0,%1,%2,%3}, [%4];" \
                 : "=r"(r0), "=r"(r1), "=r"(r2), "=r"(r3) : "r"(addr))

#define LDMX4T(r0, r1, r2, r3, addr) \
    asm volatile("ldmatrix.sync.aligned.m8n8.x4.trans.shared.b16 {%0,%1,%2,%3}, [%4];" \
                 : "=r"(r0), "=r"(r1), "=r"(r2), "=r"(r3) : "r"(addr))

#define MMA_F16(d, a0, a1, a2, a3, b0, b1) \
    asm volatile("mma.sync.aligned.m16n8k16.row.col.f32.f16.f16.f32 " \
                 "{%0,%1,%2,%3}, {%4,%5,%6,%7}, {%8,%9}, {%0,%1,%2,%3};" \
                 : "+f"((d)[0]), "+f"((d)[1]), "+f"((d)[2]), "+f"((d)[3]) \
                 : "r"(a0), "r"(a1), "r"(a2), "r"(a3), "r"(b0), "r"(b1))

__device__ __forceinline__ uint32_t pswz(uint32_t row, uint32_t nbyte) {
    uint32_t ch = nbyte >> 4;
    return row * 128 + ((ch ^ (row & 7)) << 4) + (nbyte & 15);
}

// ---------------- W prep: fp16 fragments, B-fragment order ----------------
__global__ void sp_wprep(const float* __restrict__ weight) {
    int idx  = blockIdx.x * 256 + threadIdx.x;   // 0..16383
    int lane = idx & 31;
    int q    = (idx >> 5) & 3;
    int k16  = (idx >> 7) & 7;
    int g    = idx >> 10;
    int na = (2 * q)     * 8 + (lane >> 2);
    int nb = (2 * q + 1) * 8 + (lane >> 2);
    int k0 = g * 128 + k16 * 16 + (lane & 3) * 2;
    uint4 v;
    v.x = pack_f16x2(weight[(size_t)(k0 + 0) * 64 + na], weight[(size_t)(k0 + 1) * 64 + na]);
    v.y = pack_f16x2(weight[(size_t)(k0 + 8) * 64 + na], weight[(size_t)(k0 + 9) * 64 + na]);
    v.z = pack_f16x2(weight[(size_t)(k0 + 0) * 64 + nb], weight[(size_t)(k0 + 1) * 64 + nb]);
    v.w = pack_f16x2(weight[(size_t)(k0 + 8) * 64 + nb], weight[(size_t)(k0 + 9) * 64 + nb]);
    g_wfrags[idx] = v;
}

// ---------------- main: CTA = 1 scene ----------------
__global__ __launch_bounds__(TPB, 2)
void sp_main(const float* __restrict__ hidden,
             const float* __restrict__ pos,
             const float* __restrict__ bias,
             float* __restrict__ out)
{
    extern __shared__ char smem[];
    const int tid  = threadIdx.x;
    const int lane = tid & 31;
    const int wid  = tid >> 5;
    const int b    = blockIdx.x;

    unsigned long long* sbm = (unsigned long long*)(smem + SM_BM);
    uint32_t* wor = (uint32_t*)(smem + SM_WOR);
    float* px = (float*)(smem + SM_PX);
    float* py = (float*)(smem + SM_PY);
    unsigned char* clist = (unsigned char*)(smem + SM_LIST);
    int* nact = (int*)(smem + SM_LIST + 16);

    if (tid < 64) {
        px[tid] = pos[((size_t)b * 64 + tid) * 2 + 0];
        py[tid] = pos[((size_t)b * 64 + tid) * 2 + 1];
    }
    #pragma unroll
    for (int it = 0; it < 4; it++) sbm[tid + it * TPB] = 0ull;

    // H -> smem fp16, rows of 256B, 16B-chunk XOR swizzle
    #pragma unroll
    for (int it = 0; it < 4; it++) {
        int cid = tid + it * TPB;
        int row = cid >> 4;
        int ch  = cid & 15;
        const float4* src = (const float4*)(hidden + ((size_t)b * 64 + row) * 128 + ch * 8);
        float4 v0 = src[0], v1 = src[1];
        uint4 hv;
        hv.x = pack_f16x2(v0.x, v0.y);
        hv.y = pack_f16x2(v0.z, v0.w);
        hv.z = pack_f16x2(v1.x, v1.y);
        hv.w = pack_f16x2(v1.z, v1.w);
        uint32_t off = (uint32_t)(row * 256 + ((ch ^ (row & 7)) << 4));
        *(uint4*)(smem + SM_H + off) = hv;
    }
    __syncthreads();

    // neighbor bitmasks: 4 threads per row (disjoint u16 quarters of the u64)
    {
        const int i = tid >> 2;
        const int q = tid & 3;
        const int j0 = q * 16;
        const float xi = px[i], yi = py[i];
        uint32_t acc[16];
        #pragma unroll
        for (int c = 0; c < 16; c++) acc[c] = 0u;
        #pragma unroll
        for (int jj = 0; jj < 16; jj++) {
            int j = j0 + jj;
            float dx = px[j] - xi, dy = py[j] - yi;
            if (j != i && fabsf(dx) <= 2.0f && fabsf(dy) <= 2.0f) {
                // dx+2 in [0,4] here -> trunc == floor; clamp hi only
                int gx = min(3, (int)(dx + 2.0f));
                int gy = min(3, (int)(dy + 2.0f));
                acc[gy * 4 + gx] |= (1u << jj);
            }
        }
        uint32_t bitmap = 0;
        #pragma unroll
        for (int c = 0; c < 16; c++) {
            if (acc[c]) {
                *(unsigned short*)((char*)&sbm[c * 64 + i] + q * 2) = (unsigned short)acc[c];
                bitmap |= (1u << c);
            }
        }
        uint32_t w_or = __reduce_or_sync(0xffffffffu, bitmap);
        if (lane == 0) wor[wid] = w_or;
    }
    __syncthreads();
    if (tid == 0) {
        uint32_t bm16 = 0;
        #pragma unroll
        for (int w = 0; w < 8; w++) bm16 |= wor[w];
        int n = 0;
        #pragma unroll
        for (int c = 0; c < 16; c++)
            if (bm16 & (1u << c)) clist[n++] = (unsigned char)c;
        *nact = n;
    }
    __syncthreads();

    // ---- warp mapping: (j/i strip, n-half) ----
    const int js = wid >> 1;
    const int nh = wid & 1;
    const uint32_t sbu = smem_u32(smem);

    float oacc[4][4];
    #pragma unroll
    for (int nb = 0; nb < 4; nb++) {
        oacc[nb][0] = 0.f; oacc[nb][1] = 0.f; oacc[nb][2] = 0.f; oacc[nb][3] = 0.f;
    }

    // hoist H A-fragments for all 8 k16
    const uint32_t harow = (uint32_t)(js * 16 + (lane & 7) + ((lane >> 3) & 1) * 8);
    const uint32_t hacol = (uint32_t)(lane >> 4);
    uint32_t hf[8][4];
    #pragma unroll
    for (int k16 = 0; k16 < 8; k16++) {
        const uint32_t ch  = (uint32_t)(k16 * 2) + hacol;
        const uint32_t off = harow * 256 + ((ch ^ (harow & 7)) << 4);
        LDMX4(hf[k16][0], hf[k16][1], hf[k16][2], hf[k16][3], sbu + SM_H + off);
    }

    // expansion writer mapping (fixed per thread): (cell slot, row, j-half)
    const int xs  = tid >> 7;            // 0/1 cell slot
    const int xi  = (tid >> 1) & 63;     // row
    const int xjh = tid & 1;             // 32-bit half

    // stage B M A-fragment addressing
    const uint32_t mrow = (uint32_t)(js * 16 + (lane & 7) + ((lane >> 3) & 1) * 8);

    const int na = *nact;
    for (int p0 = 0; p0 < na; p0 += 2) {
        const int nc = min(2, na - p0);
        const int g0 = clist[p0];
        const int g1 = (nc > 1) ? (int)clist[p0 + 1] : g0;
        const uint32_t slotbase = (uint32_t)(((p0 >> 1) & 1) * 16384);

        // ---- cooperative fp16 M expansion (shared; hides under stage A) ----
        {
            const int gw = (xs == 0) ? g0 : g1;
            const uint32_t bits = ((const uint32_t*)&sbm[gw * 64 + xi])[xjh];
            char* mbase = smem + SM_M + slotbase + xs * 8192 + xi * 128;
            #pragma unroll
            for (int cc = 0; cc < 4; cc++) {
                uint4 v;
                v.x = mbits16(bits >> (cc * 8 + 0));
                v.y = mbits16(bits >> (cc * 8 + 2));
                v.z = mbits16(bits >> (cc * 8 + 4));
                v.w = mbits16(bits >> (cc * 8 + 6));
                const uint32_t ch = (uint32_t)(xjh * 4 + cc);
                *(uint4*)(mbase + ((ch ^ (uint32_t)(xi & 7)) << 4)) = v;
            }
        }

        // ---- stage A: P_{g0,g1} = H @ W ----
        float pacc[2][4][4];
        #pragma unroll
        for (int s = 0; s < 2; s++)
            #pragma unroll
            for (int n8 = 0; n8 < 4; n8++) {
                pacc[s][n8][0] = 0.f; pacc[s][n8][1] = 0.f;
                pacc[s][n8][2] = 0.f; pacc[s][n8][3] = 0.f;
            }

        #pragma unroll
        for (int k16 = 0; k16 < 8; k16++) {
            uint4 w[2][2];
            #pragma unroll
            for (int qq = 0; qq < 2; qq++) {
                w[0][qq] = g_wfrags[((g0 * 8 + k16) * 4 + nh * 2 + qq) * 32 + lane];
                w[1][qq] = g_wfrags[((g1 * 8 + k16) * 4 + nh * 2 + qq) * 32 + lane];
            }
            #pragma unroll
            for (int s = 0; s < 2; s++)
                #pragma unroll
                for (int qq = 0; qq < 2; qq++) {
                    MMA_F16(pacc[s][qq * 2],     hf[k16][0], hf[k16][1], hf[k16][2], hf[k16][3],
                            w[s][qq].x, w[s][qq].y);
                    MMA_F16(pacc[s][qq * 2 + 1], hf[k16][0], hf[k16][1], hf[k16][2], hf[k16][3],
                            w[s][qq].z, w[s][qq].w);
                }
        }

        // ---- write P fp16 to smem ----
        {
            const uint32_t rowA = (uint32_t)(js * 16 + (lane >> 2));
            #pragma unroll
            for (int s = 0; s < 2; s++) {
                if (s < nc) {
                    char* basep = smem + SM_P + slotbase + s * 8192;
                    #pragma unroll
                    for (int n8 = 0; n8 < 4; n8++) {
                        const float* c = pacc[s][n8];
                        uint32_t lo = pack_f16x2(c[0], c[1]);
                        uint32_t hi = pack_f16x2(c[2], c[3]);
                        uint32_t nbyte = (uint32_t)(nh * 64 + n8 * 16 + (lane & 3) * 4);
                        *(uint32_t*)(basep + pswz(rowA, nbyte))     = lo;
                        *(uint32_t*)(basep + pswz(rowA + 8, nbyte)) = hi;
                    }
                }
            }
        }
        __syncthreads();

        // ---- stage B: out += M_s @ P_s (A-fragments via LDMX4 from M tile) ----
        #pragma unroll
        for (int s = 0; s < 2; s++) {
            if (s < nc) {
                const uint32_t mtile = sbu + SM_M + slotbase + (uint32_t)s * 8192 + mrow * 128;
                const uint32_t basep = sbu + SM_P + slotbase + (uint32_t)s * 8192;
                #pragma unroll
                for (int k16b = 0; k16b < 4; k16b++) {
                    const uint32_t chm = (uint32_t)(k16b * 2) + (uint32_t)(lane >> 4);
                    uint32_t a0, a1, a2, a3;
                    LDMX4(a0, a1, a2, a3, mtile + ((chm ^ (mrow & 7)) << 4));
                    const uint32_t rowp = (uint32_t)(k16b * 16 + (lane & 7)
                                                     + ((lane >> 3) & 1) * 8);
                    const uint32_t ch0 = (uint32_t)(nh * 4) + (uint32_t)(lane >> 4);
                    const uint32_t ch1 = ch0 + 2;
                    const uint32_t off0 = rowp * 128 + ((ch0 ^ (rowp & 7)) << 4);
                    const uint32_t off1 = rowp * 128 + ((ch1 ^ (rowp & 7)) << 4);
                    uint32_t q0, q1, q2, q3, r0, r1, r2, r3;
                    LDMX4T(q0, q1, q2, q3, basep + off0);
                    LDMX4T(r0, r1, r2, r3, basep + off1);
                    MMA_F16(oacc[0], a0, a1, a2, a3, q0, q1);
                    MMA_F16(oacc[1], a0, a1, a2, a3, q2, q3);
                    MMA_F16(oacc[2], a0, a1, a2, a3, r0, r1);
                    MMA_F16(oacc[3], a0, a1, a2, a3, r2, r3);
                }
            }
        }
    }

    // ---- epilogue ----
    {
        const int r    = js * 16 + (lane >> 2);
        const int cb   = nh * 32 + (lane & 3) * 2;
        float* orow = out + ((size_t)b * 64 + r) * 64;
        #pragma unroll
        for (int nb = 0; nb < 4; nb++) {
            const int col = cb + nb * 8;
            float2 bv = *(const float2*)(bias + col);
            *(float2*)(orow + col) =
                make_float2(oacc[nb][0] + bv.x, oacc[nb][1] + bv.y);
            *(float2*)(orow + 8 * 64 + col) =
                make_float2(oacc[nb][2] + bv.x, oacc[nb][3] + bv.y);
        }
    }
}

extern "C" void kernel_launch(void* const* d_in, const int* in_sizes, int n_in,
                              void* d_out, int out_size)
{
    const float* hidden = (const float*)d_in[0];
    const float* pos    = (const float*)d_in[1];
    const float* weight = (const float*)d_in[2];
    const float* bias   = (const float*)d_in[3];
    float* out = (float*)d_out;

    const int total = in_sizes[0] / 128;     // 16384 rows
    const int nscene = total / 64;           // 256

    sp_wprep<<<64, 256>>>(weight);

    cudaFuncSetAttribute(sp_main, cudaFuncAttributeMaxDynamicSharedMemorySize, SMEM_MAIN);
    sp_main<<<nscene, TPB, SMEM_MAIN>>>(hidden, pos, bias, out);
}